// round 1
// baseline (speedup 1.0000x reference)
#include <cuda_runtime.h>

// ExtractLearnableSlices:
//   x: (B=64, C=64, L=16384) f32
//   channel_params: (128,) f32, offset_params: (128,) f32
//   out: (B=64, N=128, W=512) f32
//
// out[b,i,j] = bilinear interp:
//   desired = sigmoid(ch[i])*(C-1); fc=floor; cc=min(fc+1,C-1); wc=frac
//   t0 = sigmoid(off[i])*(L-W); pos = t0 + j; pf=floor(pos); pc=min(pf+1,L-1); wt=frac
//   v(l) = x[b,fc,l] + wc*(x[b,cc,l]-x[b,fc,l])
//   out  = v(pf) + wt*(v(pc)-v(pf))

#define B_DIM 64
#define C_DIM 64
#define L_DIM 16384
#define N_HEADS 128
#define WIDTH 512

__global__ __launch_bounds__(WIDTH) void extract_slices_kernel(
    const float* __restrict__ x,
    const float* __restrict__ channel_params,
    const float* __restrict__ offset_params,
    float* __restrict__ out)
{
    const int i = blockIdx.x;   // head index 0..127
    const int b = blockIdx.y;   // batch 0..63
    const int j = threadIdx.x;  // 0..511

    // Per-head uniform params (computed redundantly per thread; uniform regs)
    const float cp = __ldg(&channel_params[i]);
    const float op = __ldg(&offset_params[i]);

    const float sc = 1.0f / (1.0f + expf(-cp));
    const float desired = sc * (float)(C_DIM - 1);
    const int   fc = (int)floorf(desired);
    const int   cc = min(fc + 1, C_DIM - 1);
    const float wc = desired - (float)fc;

    const float so = 1.0f / (1.0f + expf(-op));
    const float t0 = so * (float)(L_DIM - WIDTH);

    // Per-element time position (matches reference: pos = t0 + j in f32)
    const float pos = t0 + (float)j;
    const int   pf = (int)floorf(pos);
    const int   pc = min(pf + 1, L_DIM - 1);
    const float wt = pos - (float)pf;

    const size_t base = (size_t)b * (C_DIM * (size_t)L_DIM);
    const float* __restrict__ xf = x + base + (size_t)fc * L_DIM;
    const float* __restrict__ xc = x + base + (size_t)cc * L_DIM;

    const float a0 = xf[pf];
    const float a1 = xf[pc];
    const float b0 = xc[pf];
    const float b1 = xc[pc];

    const float v0 = a0 + wc * (b0 - a0);
    const float v1 = a1 + wc * (b1 - a1);
    const float r  = v0 + wt * (v1 - v0);

    out[((size_t)b * N_HEADS + i) * WIDTH + j] = r;
}

extern "C" void kernel_launch(void* const* d_in, const int* in_sizes, int n_in,
                              void* d_out, int out_size)
{
    const float* x  = (const float*)d_in[0];
    const float* ch = (const float*)d_in[1];
    const float* of = (const float*)d_in[2];
    float* out = (float*)d_out;

    dim3 grid(N_HEADS, B_DIM);
    extract_slices_kernel<<<grid, WIDTH>>>(x, ch, of, out);
}

// round 2
// speedup vs baseline: 1.5394x; 1.5394x over previous
#include <cuda_runtime.h>

// ExtractLearnableSlices — smem-staged fused channel lerp.
//   x: (B=64, C=64, L=16384) f32
//   channel_params: (128,) f32, offset_params: (128,) f32
//   out: (B=64, N=128, W=512) f32
//
// Per head i: fc/cc/wc and t0 are uniform. Stage v[l] = xf[l] + wc*(xc[l]-xf[l])
// for the 520-float window around [floor(t0)-1, floor(t0)+513] into smem once,
// then out[j] = v[pf] + wt*(v[pf+1]-v[pf]) with pos = t0 + j (f32, same as ref).

#define B_DIM   64
#define C_DIM   64
#define L_DIM   16384
#define N_HEADS 128
#define WIDTH   512

#define THREADS 128
#define OUT_PER_THREAD 4          // 128 * 4 = 512 outputs
#define SMEM_FLOATS 520           // 130 float4
#define NSTAGE4 130               // float4 tiles to stage

__global__ __launch_bounds__(THREADS) void extract_slices_kernel(
    const float* __restrict__ x,
    const float* __restrict__ channel_params,
    const float* __restrict__ offset_params,
    float* __restrict__ out)
{
    __shared__ float v[SMEM_FLOATS];

    const int i   = blockIdx.x;   // head 0..127
    const int b   = blockIdx.y;   // batch 0..63
    const int tid = threadIdx.x;  // 0..127

    // ---- per-head uniform params (redundant per thread; cheap, amortized x4) ----
    const float cp = __ldg(&channel_params[i]);
    const float op = __ldg(&offset_params[i]);

    const float sc      = 1.0f / (1.0f + expf(-cp));
    const float desired = sc * (float)(C_DIM - 1);
    const int   fc      = (int)floorf(desired);
    const int   cc      = min(fc + 1, C_DIM - 1);
    const float wc      = desired - (float)fc;

    const float so = 1.0f / (1.0f + expf(-op));
    const float t0 = so * (float)(L_DIM - WIDTH);

    const int pf0 = (int)floorf(t0);
    // float4-aligned staging origin, one element of slack below pf0
    const int l0  = (pf0 - 1) & ~3;

    const size_t base = (size_t)b * (size_t)(C_DIM * L_DIM);
    const float4* __restrict__ xf4 =
        (const float4*)(x + base + (size_t)fc * L_DIM + l0);
    const float4* __restrict__ xc4 =
        (const float4*)(x + base + (size_t)cc * L_DIM + l0);

    // ---- stage fused channel lerp into smem (130 float4 over 128 threads) ----
    float4* __restrict__ v4 = (float4*)v;
    #pragma unroll
    for (int t = tid; t < NSTAGE4; t += THREADS) {
        const float4 a = xf4[t];
        const float4 c = xc4[t];
        float4 r;
        r.x = a.x + wc * (c.x - a.x);
        r.y = a.y + wc * (c.y - a.y);
        r.z = a.z + wc * (c.z - a.z);
        r.w = a.w + wc * (c.w - a.w);
        v4[t] = r;
    }
    __syncthreads();

    // ---- time lerp from smem: 4 outputs per thread, stride-128 (conflict-free) ----
    float* __restrict__ orow = out + ((size_t)b * N_HEADS + i) * WIDTH;

    #pragma unroll
    for (int k = 0; k < OUT_PER_THREAD; ++k) {
        const int   j   = tid + k * THREADS;
        const float pos = t0 + (float)j;            // matches reference f32 math
        const float pff = floorf(pos);
        const float wt  = pos - pff;
        const int   idx = (int)pff - l0;            // in [0, 517]
        const float v0  = v[idx];
        const float v1  = v[idx + 1];
        orow[j] = v0 + wt * (v1 - v0);
    }
}

extern "C" void kernel_launch(void* const* d_in, const int* in_sizes, int n_in,
                              void* d_out, int out_size)
{
    const float* x  = (const float*)d_in[0];
    const float* ch = (const float*)d_in[1];
    const float* of = (const float*)d_in[2];
    float* out = (float*)d_out;

    dim3 grid(N_HEADS, B_DIM);
    extract_slices_kernel<<<grid, THREADS>>>(x, ch, of, out);
}